// round 1
// baseline (speedup 1.0000x reference)
#include <cuda_runtime.h>

// Problem constants (from reference)
#define MULc 16
#define Dc 4
#define S0c 8
#define S1c 8
#define SOUTc 8
#define P3c 8
#define P4c 4

#define EPB 16        // edges per block (16 threads per edge)
#define NTHREADS 256

__global__ __launch_bounds__(NTHREADS) void tp_kernel(
    const float* __restrict__ x0, const int* __restrict__ i0,
    const float* __restrict__ x1, const float* __restrict__ C3,
    const float* __restrict__ C4, const int* __restrict__ p3,
    const int* __restrict__ p4, float* __restrict__ out, int E)
{
    __shared__ float sC3[P3c * 64];       // 2 KB
    __shared__ float sC4[P4c * 256];      // 4 KB
    __shared__ int   sp3[P3c * 3];
    __shared__ int   sp4[P4c * 4];
    __shared__ float sW[EPB][P3c + P4c][16];   // 12 KB: per-edge 4x4 W per path
    __shared__ float sx1[EPB][S1c * Dc];       // 2 KB

    const int tid = threadIdx.x;

    // Stage constants (tiny)
    for (int t = tid; t < P3c * 64; t += NTHREADS) sC3[t] = C3[t];
    for (int t = tid; t < P4c * 256; t += NTHREADS) sC4[t] = C4[t];
    if (tid < P3c * 3) sp3[tid] = p3[tid];
    if (tid < P4c * 4) sp4[tid] = p4[tid];

    const int eL = tid >> 4;      // edge slot within block
    const int u  = tid & 15;      // mul index
    const int e  = blockIdx.x * EPB + eL;
    const bool valid = (e < E);

    // Stage x1 row for this edge (32 floats, 2 per thread)
    if (valid) {
        const float2* src = reinterpret_cast<const float2*>(x1 + (size_t)e * (S1c * Dc));
        reinterpret_cast<float2*>(sx1[eL])[u] = src[u];
    }
    __syncthreads();

    // ---- W build: thread u of each edge computes entry (i = u>>2, k = u&3)
    //      of W_p for all 12 paths.
    if (valid) {
        const int i = u >> 2;
        const int k = u & 3;
        const float* bb = sx1[eL];
        #pragma unroll
        for (int p = 0; p < P3c; p++) {
            const float* b  = bb + sp3[p * 3 + 1] * 4;
            const float* c3 = sC3 + p * 64 + i * 16 + k;     // stride 4 over j
            float w = fmaf(b[0], c3[0],
                      fmaf(b[1], c3[4],
                      fmaf(b[2], c3[8],
                           b[3] * c3[12])));
            sW[eL][p][i * 4 + k] = w;
        }
        #pragma unroll
        for (int p = 0; p < P4c; p++) {
            const float* b  = bb + sp4[p * 4 + 1] * 4;
            const float* c  = bb + sp4[p * 4 + 2] * 4;
            const float* c4 = sC4 + p * 256 + i * 64 + k;    // [j][l] strides 16, 4
            float w = 0.f;
            #pragma unroll
            for (int j = 0; j < 4; j++) {
                #pragma unroll
                for (int l = 0; l < 4; l++)
                    w = fmaf(b[j] * c[l], c4[j * 16 + l * 4], w);
            }
            sW[eL][P3c + p][i * 4 + k] = w;
        }
    }
    __syncthreads();

    if (!valid) return;

    // Path metadata into registers (compile-time indexed -> stays in regs)
    int s3[P3c], z3[P3c], s4[P4c], z4[P4c];
    #pragma unroll
    for (int p = 0; p < P3c; p++) { s3[p] = sp3[p * 3 + 0]; z3[p] = sp3[p * 3 + 2]; }
    #pragma unroll
    for (int p = 0; p < P4c; p++) { s4[p] = sp4[p * 4 + 0]; z4[p] = sp4[p * 4 + 3]; }

    const float4* arow = reinterpret_cast<const float4*>(
        x0 + (size_t)__ldg(&i0[e]) * (S0c * MULc * Dc));
    float4* orow = reinterpret_cast<float4*>(out + (size_t)e * (SOUTc * MULc * Dc));

    // Output segment loop at compile time; path match is warp-uniform
    #pragma unroll
    for (int z = 0; z < SOUTc; z++) {
        float r0 = 0.f, r1 = 0.f, r2 = 0.f, r3 = 0.f;
        #pragma unroll
        for (int p = 0; p < P3c; p++) {
            if (z3[p] == z) {
                const float4 av = __ldg(&arow[s3[p] * MULc + u]);
                const float* w = sW[eL][p];
                r0 = fmaf(av.x, w[0],  fmaf(av.y, w[4],  fmaf(av.z, w[8],  fmaf(av.w, w[12], r0))));
                r1 = fmaf(av.x, w[1],  fmaf(av.y, w[5],  fmaf(av.z, w[9],  fmaf(av.w, w[13], r1))));
                r2 = fmaf(av.x, w[2],  fmaf(av.y, w[6],  fmaf(av.z, w[10], fmaf(av.w, w[14], r2))));
                r3 = fmaf(av.x, w[3],  fmaf(av.y, w[7],  fmaf(av.z, w[11], fmaf(av.w, w[15], r3))));
            }
        }
        #pragma unroll
        for (int p = 0; p < P4c; p++) {
            if (z4[p] == z) {
                const float4 av = __ldg(&arow[s4[p] * MULc + u]);
                const float* w = sW[eL][P3c + p];
                r0 = fmaf(av.x, w[0],  fmaf(av.y, w[4],  fmaf(av.z, w[8],  fmaf(av.w, w[12], r0))));
                r1 = fmaf(av.x, w[1],  fmaf(av.y, w[5],  fmaf(av.z, w[9],  fmaf(av.w, w[13], r1))));
                r2 = fmaf(av.x, w[2],  fmaf(av.y, w[6],  fmaf(av.z, w[10], fmaf(av.w, w[14], r2))));
                r3 = fmaf(av.x, w[3],  fmaf(av.y, w[7],  fmaf(av.z, w[11], fmaf(av.w, w[15], r3))));
            }
        }
        orow[z * MULc + u] = make_float4(r0, r1, r2, r3);
    }
}

extern "C" void kernel_launch(void* const* d_in, const int* in_sizes, int n_in,
                              void* d_out, int out_size) {
    const float* x0 = (const float*)d_in[0];
    const int*   i0 = (const int*)d_in[1];
    const float* x1 = (const float*)d_in[2];
    const float* C3 = (const float*)d_in[3];
    const float* C4 = (const float*)d_in[4];
    const int*   p3 = (const int*)d_in[5];
    const int*   p4 = (const int*)d_in[6];

    const int E = in_sizes[1];                 // i0 element count
    const int blocks = (E + EPB - 1) / EPB;
    tp_kernel<<<blocks, NTHREADS>>>(x0, i0, x1, C3, C4, p3, p4, (float*)d_out, E);
}